// round 11
// baseline (speedup 1.0000x reference)
#include <cuda_runtime.h>

// Lorenz96 RK4, batch x 40 fp32.
// R7 structure: fma.rn.f32x2 packed row pairs (rows r, r+3 of 6-row warp
// windows), 10 threads per row-pair, halos via 64-bit shuffles,
// prefetch-distance-1 pipeline, ITERS=4 (grid ~2731 CTAs, 4 CTAs/SM).
// New: guard-free interior fast path + 32-bit indexing.

#define N_STATE 40
#define TPB 256
#define WARPS_PER_BLOCK (TPB / 32)
#define ROWS_PER_WARP 6
#define ITERS 4
#define ROWS_PER_BLOCK_TOTAL (WARPS_PER_BLOCK * ROWS_PER_WARP * ITERS)  // 192

typedef unsigned long long ull;

__device__ __forceinline__ ull pack2(float lo, float hi) {
    ull r;
    asm("mov.b64 %0, {%1, %2};" : "=l"(r) : "f"(lo), "f"(hi));
    return r;
}
__device__ __forceinline__ void unpack2(ull v, float& lo, float& hi) {
    asm("mov.b64 {%0, %1}, %2;" : "=f"(lo), "=f"(hi) : "l"(v));
}
__device__ __forceinline__ ull fma2(ull a, ull b, ull c) {
    ull d;
    asm("fma.rn.f32x2 %0, %1, %2, %3;" : "=l"(d) : "l"(a), "l"(b), "l"(c));
    return d;
}

#define NEG1_2 0xBF800000BF800000ULL   // (-1, -1)
#define ONE_2  0x3F8000003F800000ULL   // ( 1,  1)
#define TWO_2  0x4000000040000000ULL   // ( 2,  2)
#define F_2    0x4100000041000000ULL   // ( 8,  8)  FORCE

template <bool FIRST, bool HAS_NEXT>
__device__ __forceinline__ void stage(const ull* __restrict__ y,
                                      ull* __restrict__ acc,
                                      const ull* __restrict__ x,
                                      ull* __restrict__ yn,
                                      ull W2, ull C2,
                                      unsigned mask, int left, int right) {
    const ull hL2 = __shfl_sync(mask, y[2], left);   // i-2 at e=0
    const ull hL3 = __shfl_sync(mask, y[3], left);   // i-1 at e=0, i-2 at e=1
    const ull hR0 = __shfl_sync(mask, y[0], right);  // i+1 at e=3

    const ull yp1[4] = { y[1], y[2], y[3], hR0 };
    const ull ym1[4] = { hL3,  y[0], y[1], y[2] };
    const ull ym2[4] = { hL2,  hL3,  y[0], y[1] };

#pragma unroll
    for (int e = 0; e < 4; e++) {
        const ull d = fma2(ym2[e], NEG1_2, yp1[e]);   // y_{i+1} - y_{i-2}
        const ull t = fma2(y[e],   NEG1_2, F_2);      // F - y_i
        const ull k = fma2(d, ym1[e], t);
        if (FIRST)
            acc[e] = k;
        else
            acc[e] = fma2(k, W2, acc[e]);
        if (HAS_NEXT)
            yn[e] = fma2(k, C2, x[e]);
    }
}

__device__ __forceinline__ void compute_window(const float4& va, const float4& vb,
                                               float4& oa, float4& ob,
                                               ull hdt2, ull dt2, ull sdt2,
                                               unsigned mask, int left, int right) {
    ull x[4] = { pack2(va.x, vb.x), pack2(va.y, vb.y),
                 pack2(va.z, vb.z), pack2(va.w, vb.w) };
    ull acc[4], ya[4], yb[4];

    stage<true,  true >(x,  acc, x, ya, ONE_2, hdt2, mask, left, right);
    stage<false, true >(ya, acc, x, yb, TWO_2, hdt2, mask, left, right);
    stage<false, true >(yb, acc, x, ya, TWO_2, dt2,  mask, left, right);
    stage<false, false>(ya, acc, x, yb, ONE_2, dt2,  mask, left, right);

    unpack2(fma2(acc[0], sdt2, x[0]), oa.x, ob.x);
    unpack2(fma2(acc[1], sdt2, x[1]), oa.y, ob.y);
    unpack2(fma2(acc[2], sdt2, x[2]), oa.z, ob.z);
    unpack2(fma2(acc[3], sdt2, x[3]), oa.w, ob.w);
}

__global__ __launch_bounds__(TPB, 4)
void lorenz96_rk4_kernel(const float4* __restrict__ x0,
                         const float* __restrict__ dt_ptr,
                         float4* __restrict__ out,
                         int batch) {
    const int lane = threadIdx.x & 31;
    if (lane >= 30) return;                 // lanes 30,31 idle (in no shfl mask)

    const int g = (lane >= 20) ? 2 : (lane >= 10 ? 1 : 0);  // row-pair group
    const int t = lane - g * 10;                            // element chunk

    const int warp = blockIdx.x * WARPS_PER_BLOCK + (threadIdx.x >> 5);
    const int row0 = warp * (ROWS_PER_WARP * ITERS) + g;    // 32-bit throughout

    const unsigned mask = 0x3FFu << (g * 10);
    const int base = g * 10;
    const int left  = (t == 0) ? base + 9 : lane - 1;
    const int right = (t == 9) ? base     : lane + 1;

    const float dt = __ldg(dt_ptr);
    const ull dt2  = pack2(dt, dt);
    const ull hdt2 = pack2(0.5f * dt, 0.5f * dt);
    const float sdt = dt * (1.0f / 6.0f);
    const ull sdt2 = pack2(sdt, sdt);

    const float4* __restrict__ pin  = x0  + (row0 * 10 + t);
    float4*       __restrict__ pout = out + (row0 * 10 + t);

    // ---- Interior fast path: entire 24-row warp chunk in range (all full
    // blocks; only the last block takes the tail). Zero predication. ----
    if (row0 - g + ROWS_PER_WARP * ITERS <= batch) {
        float4 a0 = pin[0];
        float4 b0 = pin[30];

#pragma unroll
        for (int i = 0; i < ITERS; i++) {
            float4 a1, b1;
            if (i + 1 < ITERS) {           // compile-time; loads unconditional
                a1 = pin[(i + 1) * 60];
                b1 = pin[(i + 1) * 60 + 30];
            }

            float4 oa, ob;
            compute_window(a0, b0, oa, ob, hdt2, dt2, sdt2, mask, left, right);
            pout[i * 60]      = oa;
            pout[i * 60 + 30] = ob;

            a0 = a1; b0 = b1;
        }
        return;
    }

    // ---- Tail path (last block only): fully guarded ----
    for (int i = 0; i < ITERS; i++) {
        const int r = row0 + i * ROWS_PER_WARP;
        if (r >= batch) break;
        const bool bOK = (r + 3 < batch);
        const float4 va = pin[i * 60];
        const float4 vb = bOK ? pin[i * 60 + 30] : va;

        float4 oa, ob;
        compute_window(va, vb, oa, ob, hdt2, dt2, sdt2, mask, left, right);
        pout[i * 60] = oa;
        if (bOK) pout[i * 60 + 30] = ob;
    }
}

extern "C" void kernel_launch(void* const* d_in, const int* in_sizes, int n_in,
                              void* d_out, int out_size) {
    const float4* x0 = (const float4*)d_in[0];
    // d_in[1] is t (unused, autonomous system)
    const float* dt = (const float*)d_in[2];
    float4* out = (float4*)d_out;

    const int batch = in_sizes[0] / N_STATE;
    const int blocks = (batch + ROWS_PER_BLOCK_TOTAL - 1) / ROWS_PER_BLOCK_TOTAL;
    lorenz96_rk4_kernel<<<blocks, TPB>>>(x0, dt, out, batch);
}

// round 12
// speedup vs baseline: 1.0110x; 1.0110x over previous
#include <cuda_runtime.h>

// Lorenz96 RK4, batch x 40 fp32.
// R5 compute body (fma.rn.f32x2, rows r/r+3 packed, 10 threads per row-pair,
// halos via 64-bit shuffles) + software-pipelined grid chunks:
// each warp-group processes ITERS consecutive 6-row windows, prefetching the
// next window's loads before computing the current one.
// R12: identical to R7 + streaming cache hints (__ldcs/__stcs) on the
// once-touched data stream.

#define N_STATE 40
#define TPB 256
#define WARPS_PER_BLOCK (TPB / 32)
#define ROWS_PER_WARP 6
#define ITERS 4

typedef unsigned long long ull;

__device__ __forceinline__ ull pack2(float lo, float hi) {
    ull r;
    asm("mov.b64 %0, {%1, %2};" : "=l"(r) : "f"(lo), "f"(hi));
    return r;
}
__device__ __forceinline__ void unpack2(ull v, float& lo, float& hi) {
    asm("mov.b64 {%0, %1}, %2;" : "=f"(lo), "=f"(hi) : "l"(v));
}
__device__ __forceinline__ ull fma2(ull a, ull b, ull c) {
    ull d;
    asm("fma.rn.f32x2 %0, %1, %2, %3;" : "=l"(d) : "l"(a), "l"(b), "l"(c));
    return d;
}

#define NEG1_2 0xBF800000BF800000ULL   // (-1, -1)
#define ONE_2  0x3F8000003F800000ULL   // ( 1,  1)
#define TWO_2  0x4000000040000000ULL   // ( 2,  2)
#define F_2    0x4100000041000000ULL   // ( 8,  8)  FORCE

template <bool FIRST, bool HAS_NEXT>
__device__ __forceinline__ void stage(const ull* __restrict__ y,
                                      ull* __restrict__ acc,
                                      const ull* __restrict__ x,
                                      ull* __restrict__ yn,
                                      ull W2, ull C2,
                                      unsigned mask, int left, int right) {
    const ull hL2 = __shfl_sync(mask, y[2], left);   // i-2 at e=0
    const ull hL3 = __shfl_sync(mask, y[3], left);   // i-1 at e=0, i-2 at e=1
    const ull hR0 = __shfl_sync(mask, y[0], right);  // i+1 at e=3

    const ull yp1[4] = { y[1], y[2], y[3], hR0 };
    const ull ym1[4] = { hL3,  y[0], y[1], y[2] };
    const ull ym2[4] = { hL2,  hL3,  y[0], y[1] };

#pragma unroll
    for (int e = 0; e < 4; e++) {
        const ull d = fma2(ym2[e], NEG1_2, yp1[e]);   // y_{i+1} - y_{i-2}
        const ull t = fma2(y[e],   NEG1_2, F_2);      // F - y_i
        const ull k = fma2(d, ym1[e], t);
        if (FIRST)
            acc[e] = k;
        else
            acc[e] = fma2(k, W2, acc[e]);
        if (HAS_NEXT)
            yn[e] = fma2(k, C2, x[e]);
    }
}

__global__ __launch_bounds__(TPB, 4)
void lorenz96_rk4_kernel(const float4* __restrict__ x0,
                         const float* __restrict__ dt_ptr,
                         float4* __restrict__ out,
                         int batch) {
    const int lane = threadIdx.x & 31;
    if (lane >= 30) return;                 // lanes 30,31 idle (in no shfl mask)

    const int g = (lane >= 20) ? 2 : (lane >= 10 ? 1 : 0);  // row-pair group
    const int t = lane - g * 10;                            // element chunk

    const int warp = blockIdx.x * WARPS_PER_BLOCK + (threadIdx.x >> 5);
    const long long row0 = (long long)warp * (ROWS_PER_WARP * ITERS) + g;

    const unsigned mask = 0x3FFu << (g * 10);
    const int base = g * 10;
    const int left  = (t == 0) ? base + 9 : lane - 1;
    const int right = (t == 9) ? base     : lane + 1;

    const float dt = __ldg(dt_ptr);
    const ull dt2  = pack2(dt, dt);
    const ull hdt2 = pack2(0.5f * dt, 0.5f * dt);
    const float sdt = dt * (1.0f / 6.0f);
    const ull sdt2 = pack2(sdt, sdt);

    const float4* __restrict__ pin  = x0  + (row0 * 10 + t);
    float4*       __restrict__ pout = out + (row0 * 10 + t);

    long long r = row0;
    bool aOK = (r < batch);
    bool bOK = (r + 3 < batch);
    float4 va, vb;
    if (aOK) va = __ldcs(pin);
    if (bOK) vb = __ldcs(pin + 30);

#pragma unroll
    for (int i = 0; i < ITERS; i++) {
        // ---- Prefetch next window (rows +6) before computing current ----
        float4 na, nb;
        bool naOK = false, nbOK = false;
        if (i + 1 < ITERS) {
            const long long rn = r + ROWS_PER_WARP;
            naOK = (rn < batch);
            nbOK = (rn + 3 < batch);
            if (naOK) na = __ldcs(pin + 60);
            if (nbOK) nb = __ldcs(pin + 90);
        }

        // ---- Compute current window (guarded; uniform within 10-lane group) ----
        if (aOK) {
            const float4 vbs = bOK ? vb : va;
            ull x[4] = { pack2(va.x, vbs.x), pack2(va.y, vbs.y),
                         pack2(va.z, vbs.z), pack2(va.w, vbs.w) };
            ull acc[4], ya[4], yb[4];

            stage<true,  true >(x,  acc, x, ya, ONE_2, hdt2, mask, left, right);
            stage<false, true >(ya, acc, x, yb, TWO_2, hdt2, mask, left, right);
            stage<false, true >(yb, acc, x, ya, TWO_2, dt2,  mask, left, right);
            stage<false, false>(ya, acc, x, yb, ONE_2, dt2,  mask, left, right);

            float4 oa, ob;
            unpack2(fma2(acc[0], sdt2, x[0]), oa.x, ob.x);
            unpack2(fma2(acc[1], sdt2, x[1]), oa.y, ob.y);
            unpack2(fma2(acc[2], sdt2, x[2]), oa.z, ob.z);
            unpack2(fma2(acc[3], sdt2, x[3]), oa.w, ob.w);

            __stcs(pout, oa);
            if (bOK) __stcs(pout + 30, ob);
        }

        va = na; vb = nb;
        aOK = naOK; bOK = nbOK;
        r += ROWS_PER_WARP;
        pin += 60; pout += 60;
    }
}

extern "C" void kernel_launch(void* const* d_in, const int* in_sizes, int n_in,
                              void* d_out, int out_size) {
    const float4* x0 = (const float4*)d_in[0];
    // d_in[1] is t (unused, autonomous system)
    const float* dt = (const float*)d_in[2];
    float4* out = (float4*)d_out;

    const int batch = in_sizes[0] / N_STATE;
    const int rows_per_block = WARPS_PER_BLOCK * ROWS_PER_WARP * ITERS;  // 192
    const int blocks = (batch + rows_per_block - 1) / rows_per_block;
    lorenz96_rk4_kernel<<<blocks, TPB>>>(x0, dt, out, batch);
}

// round 13
// speedup vs baseline: 1.1395x; 1.1271x over previous
#include <cuda_runtime.h>
#include <cstdint>

// Lorenz96 RK4, batch x 40 fp32.
// Input staged via cp.async.bulk (async proxy) into 4 smem tiles per CTA,
// all issued up-front (prefetch depth 4, zero register cost).
// Compute: fma.rn.f32x2 packed row pairs (rows r, r+3 of 6-row warp windows),
// 10 threads per row-pair, halos via 64-bit shuffles. Direct coalesced stores.

#define N_STATE 40
#define TPB 256
#define WARPS_PER_BLOCK 8
#define ROWS_PER_WARP 6
#define ROWS_PER_TILE 48                      // 8 warps x 6 rows
#define NTILES 4
#define ROWS_PER_CTA (ROWS_PER_TILE * NTILES) // 192
#define VECS_PER_TILE (ROWS_PER_TILE * 10)    // 480 float4
#define TILE_BYTES (VECS_PER_TILE * 16)       // 7680

typedef unsigned long long ull;

__device__ __forceinline__ uint32_t smem_u32(const void* p) {
    uint32_t a;
    asm("{ .reg .u64 t; cvta.to.shared.u64 t, %1; cvt.u32.u64 %0, t; }"
        : "=r"(a) : "l"(p));
    return a;
}
__device__ __forceinline__ void mbar_init(uint32_t mbar, uint32_t count) {
    asm volatile("mbarrier.init.shared.b64 [%0], %1;" :: "r"(mbar), "r"(count) : "memory");
}
__device__ __forceinline__ void mbar_expect_tx(uint32_t mbar, uint32_t bytes) {
    asm volatile("mbarrier.arrive.expect_tx.shared.b64 _, [%0], %1;"
                 :: "r"(mbar), "r"(bytes) : "memory");
}
__device__ __forceinline__ void mbar_wait0(uint32_t mbar) {
    asm volatile(
        "{\n\t.reg .pred P;\n\t"
        "WL_%=:\n\t"
        "mbarrier.try_wait.parity.acquire.cta.shared::cta.b64 P, [%0], 0, 0x989680;\n\t"
        "@P bra WD_%=;\n\t"
        "bra WL_%=;\n\t"
        "WD_%=:\n\t}"
        :: "r"(mbar) : "memory");
}
__device__ __forceinline__ void bulk_copy(uint32_t dst_smem, const void* src,
                                          uint32_t bytes, uint32_t mbar) {
    asm volatile(
        "cp.async.bulk.shared::cluster.global.mbarrier::complete_tx::bytes "
        "[%0], [%1], %2, [%3];"
        :: "r"(dst_smem), "l"(src), "r"(bytes), "r"(mbar) : "memory");
}

__device__ __forceinline__ ull pack2(float lo, float hi) {
    ull r;
    asm("mov.b64 %0, {%1, %2};" : "=l"(r) : "f"(lo), "f"(hi));
    return r;
}
__device__ __forceinline__ void unpack2(ull v, float& lo, float& hi) {
    asm("mov.b64 {%0, %1}, %2;" : "=f"(lo), "=f"(hi) : "l"(v));
}
__device__ __forceinline__ ull fma2(ull a, ull b, ull c) {
    ull d;
    asm("fma.rn.f32x2 %0, %1, %2, %3;" : "=l"(d) : "l"(a), "l"(b), "l"(c));
    return d;
}

#define NEG1_2 0xBF800000BF800000ULL   // (-1, -1)
#define ONE_2  0x3F8000003F800000ULL   // ( 1,  1)
#define TWO_2  0x4000000040000000ULL   // ( 2,  2)
#define F_2    0x4100000041000000ULL   // ( 8,  8)  FORCE

template <bool FIRST, bool HAS_NEXT>
__device__ __forceinline__ void stage(const ull* __restrict__ y,
                                      ull* __restrict__ acc,
                                      const ull* __restrict__ x,
                                      ull* __restrict__ yn,
                                      ull W2, ull C2,
                                      unsigned mask, int left, int right) {
    const ull hL2 = __shfl_sync(mask, y[2], left);   // i-2 at e=0
    const ull hL3 = __shfl_sync(mask, y[3], left);   // i-1 at e=0, i-2 at e=1
    const ull hR0 = __shfl_sync(mask, y[0], right);  // i+1 at e=3

    const ull yp1[4] = { y[1], y[2], y[3], hR0 };
    const ull ym1[4] = { hL3,  y[0], y[1], y[2] };
    const ull ym2[4] = { hL2,  hL3,  y[0], y[1] };

#pragma unroll
    for (int e = 0; e < 4; e++) {
        const ull d = fma2(ym2[e], NEG1_2, yp1[e]);   // y_{i+1} - y_{i-2}
        const ull t = fma2(y[e],   NEG1_2, F_2);      // F - y_i
        const ull k = fma2(d, ym1[e], t);
        if (FIRST)
            acc[e] = k;
        else
            acc[e] = fma2(k, W2, acc[e]);
        if (HAS_NEXT)
            yn[e] = fma2(k, C2, x[e]);
    }
}

__global__ __launch_bounds__(TPB)
void lorenz96_rk4_kernel(const float4* __restrict__ x0,
                         const float* __restrict__ dt_ptr,
                         float4* __restrict__ out,
                         int batch) {
    __shared__ alignas(128) float4 tiles[NTILES][VECS_PER_TILE];
    __shared__ alignas(8) ull mbar[NTILES];

    const int tid = threadIdx.x;
    const int base_row = blockIdx.x * ROWS_PER_CTA;
    const uint32_t mb0 = smem_u32(&mbar[0]);

    if (tid == 0) {
#pragma unroll
        for (int s = 0; s < NTILES; s++)
            mbar_init(mb0 + 8 * s, 1);
    }
    __syncthreads();

    // Producer: issue all tile copies up-front (async engine holds the MLP).
    if (tid == 0) {
#pragma unroll
        for (int s = 0; s < NTILES; s++) {
            int rows = batch - base_row - s * ROWS_PER_TILE;
            rows = rows < 0 ? 0 : (rows > ROWS_PER_TILE ? ROWS_PER_TILE : rows);
            if (rows > 0) {
                const uint32_t bytes = (uint32_t)rows * (N_STATE * 4);
                mbar_expect_tx(mb0 + 8 * s, bytes);
                bulk_copy(smem_u32(&tiles[s][0]),
                          x0 + (size_t)(base_row + s * ROWS_PER_TILE) * 10,
                          bytes, mb0 + 8 * s);
            }
        }
    }

    const int lane = tid & 31;
    if (lane >= 30) return;                 // lanes 30,31 idle (in no shfl mask)

    const int g = (lane >= 20) ? 2 : (lane >= 10 ? 1 : 0);  // row-pair group
    const int t = lane - g * 10;                            // element chunk
    const int warp = tid >> 5;

    const unsigned mask = 0x3FFu << (g * 10);
    const int base = g * 10;
    const int left  = (t == 0) ? base + 9 : lane - 1;
    const int right = (t == 9) ? base     : lane + 1;

    const float dt = __ldg(dt_ptr);
    const ull dt2  = pack2(dt, dt);
    const ull hdt2 = pack2(0.5f * dt, 0.5f * dt);
    const float sdt = dt * (1.0f / 6.0f);
    const ull sdt2 = pack2(sdt, sdt);

    const int vi = (warp * ROWS_PER_WARP + g) * 10 + t;  // smem float4 index

#pragma unroll
    for (int s = 0; s < NTILES; s++) {
        const int row = base_row + s * ROWS_PER_TILE + warp * ROWS_PER_WARP + g;
        if (row >= batch) break;            // later tiles are also out of range
        const bool bOK = (row + 3 < batch);

        mbar_wait0(mb0 + 8 * s);

        const float4 va = tiles[s][vi];
        const float4 vb = bOK ? tiles[s][vi + 30] : va;

        ull x[4] = { pack2(va.x, vb.x), pack2(va.y, vb.y),
                     pack2(va.z, vb.z), pack2(va.w, vb.w) };
        ull acc[4], ya[4], yb[4];

        stage<true,  true >(x,  acc, x, ya, ONE_2, hdt2, mask, left, right);
        stage<false, true >(ya, acc, x, yb, TWO_2, hdt2, mask, left, right);
        stage<false, true >(yb, acc, x, ya, TWO_2, dt2,  mask, left, right);
        stage<false, false>(ya, acc, x, yb, ONE_2, dt2,  mask, left, right);

        float4 oa, ob;
        unpack2(fma2(acc[0], sdt2, x[0]), oa.x, ob.x);
        unpack2(fma2(acc[1], sdt2, x[1]), oa.y, ob.y);
        unpack2(fma2(acc[2], sdt2, x[2]), oa.z, ob.z);
        unpack2(fma2(acc[3], sdt2, x[3]), oa.w, ob.w);

        float4* __restrict__ pout = out + ((size_t)row * 10 + t);
        pout[0] = oa;
        if (bOK) pout[30] = ob;
    }
}

extern "C" void kernel_launch(void* const* d_in, const int* in_sizes, int n_in,
                              void* d_out, int out_size) {
    const float4* x0 = (const float4*)d_in[0];
    // d_in[1] is t (unused, autonomous system)
    const float* dt = (const float*)d_in[2];
    float4* out = (float4*)d_out;

    const int batch = in_sizes[0] / N_STATE;
    const int blocks = (batch + ROWS_PER_CTA - 1) / ROWS_PER_CTA;
    lorenz96_rk4_kernel<<<blocks, TPB>>>(x0, dt, out, batch);
}

// round 14
// speedup vs baseline: 1.1454x; 1.0052x over previous
#include <cuda_runtime.h>
#include <cstdint>

// Lorenz96 RK4, batch x 40 fp32.
// Input staged via cp.async.bulk into 4 smem tiles per CTA, all issued
// up-front (prefetch depth 4, zero register cost).
// Compute: fma.rn.f32x2 packed row pairs (rows r, r+3 of 6-row warp windows),
// 10 threads per row-pair, halos via 64-bit shuffles. Direct coalesced stores.
// R14: force 5 CTAs/SM (reg cap 48) + incremental per-tile addressing.

#define N_STATE 40
#define TPB 256
#define WARPS_PER_BLOCK 8
#define ROWS_PER_WARP 6
#define ROWS_PER_TILE 48                      // 8 warps x 6 rows
#define NTILES 4
#define ROWS_PER_CTA (ROWS_PER_TILE * NTILES) // 192
#define VECS_PER_TILE (ROWS_PER_TILE * 10)    // 480 float4
#define TILE_BYTES (VECS_PER_TILE * 16)       // 7680

typedef unsigned long long ull;

__device__ __forceinline__ uint32_t smem_u32(const void* p) {
    uint32_t a;
    asm("{ .reg .u64 t; cvta.to.shared.u64 t, %1; cvt.u32.u64 %0, t; }"
        : "=r"(a) : "l"(p));
    return a;
}
__device__ __forceinline__ void mbar_init(uint32_t mbar, uint32_t count) {
    asm volatile("mbarrier.init.shared.b64 [%0], %1;" :: "r"(mbar), "r"(count) : "memory");
}
__device__ __forceinline__ void mbar_expect_tx(uint32_t mbar, uint32_t bytes) {
    asm volatile("mbarrier.arrive.expect_tx.shared.b64 _, [%0], %1;"
                 :: "r"(mbar), "r"(bytes) : "memory");
}
__device__ __forceinline__ void mbar_wait0(uint32_t mbar) {
    asm volatile(
        "{\n\t.reg .pred P;\n\t"
        "WL_%=:\n\t"
        "mbarrier.try_wait.parity.acquire.cta.shared::cta.b64 P, [%0], 0, 0x989680;\n\t"
        "@P bra WD_%=;\n\t"
        "bra WL_%=;\n\t"
        "WD_%=:\n\t}"
        :: "r"(mbar) : "memory");
}
__device__ __forceinline__ void bulk_copy(uint32_t dst_smem, const void* src,
                                          uint32_t bytes, uint32_t mbar) {
    asm volatile(
        "cp.async.bulk.shared::cluster.global.mbarrier::complete_tx::bytes "
        "[%0], [%1], %2, [%3];"
        :: "r"(dst_smem), "l"(src), "r"(bytes), "r"(mbar) : "memory");
}

__device__ __forceinline__ ull pack2(float lo, float hi) {
    ull r;
    asm("mov.b64 %0, {%1, %2};" : "=l"(r) : "f"(lo), "f"(hi));
    return r;
}
__device__ __forceinline__ void unpack2(ull v, float& lo, float& hi) {
    asm("mov.b64 {%0, %1}, %2;" : "=f"(lo), "=f"(hi) : "l"(v));
}
__device__ __forceinline__ ull fma2(ull a, ull b, ull c) {
    ull d;
    asm("fma.rn.f32x2 %0, %1, %2, %3;" : "=l"(d) : "l"(a), "l"(b), "l"(c));
    return d;
}

#define NEG1_2 0xBF800000BF800000ULL   // (-1, -1)
#define ONE_2  0x3F8000003F800000ULL   // ( 1,  1)
#define TWO_2  0x4000000040000000ULL   // ( 2,  2)
#define F_2    0x4100000041000000ULL   // ( 8,  8)  FORCE

template <bool FIRST, bool HAS_NEXT>
__device__ __forceinline__ void stage(const ull* __restrict__ y,
                                      ull* __restrict__ acc,
                                      const ull* __restrict__ x,
                                      ull* __restrict__ yn,
                                      ull W2, ull C2,
                                      unsigned mask, int left, int right) {
    const ull hL2 = __shfl_sync(mask, y[2], left);   // i-2 at e=0
    const ull hL3 = __shfl_sync(mask, y[3], left);   // i-1 at e=0, i-2 at e=1
    const ull hR0 = __shfl_sync(mask, y[0], right);  // i+1 at e=3

    const ull yp1[4] = { y[1], y[2], y[3], hR0 };
    const ull ym1[4] = { hL3,  y[0], y[1], y[2] };
    const ull ym2[4] = { hL2,  hL3,  y[0], y[1] };

#pragma unroll
    for (int e = 0; e < 4; e++) {
        const ull d = fma2(ym2[e], NEG1_2, yp1[e]);   // y_{i+1} - y_{i-2}
        const ull t = fma2(y[e],   NEG1_2, F_2);      // F - y_i
        const ull k = fma2(d, ym1[e], t);
        if (FIRST)
            acc[e] = k;
        else
            acc[e] = fma2(k, W2, acc[e]);
        if (HAS_NEXT)
            yn[e] = fma2(k, C2, x[e]);
    }
}

__global__ __launch_bounds__(TPB, 5)
void lorenz96_rk4_kernel(const float4* __restrict__ x0,
                         const float* __restrict__ dt_ptr,
                         float4* __restrict__ out,
                         int batch) {
    __shared__ alignas(128) float4 tiles[NTILES][VECS_PER_TILE];
    __shared__ alignas(8) ull mbar[NTILES];

    const int tid = threadIdx.x;
    const int base_row = blockIdx.x * ROWS_PER_CTA;
    const uint32_t mb0 = smem_u32(&mbar[0]);

    if (tid == 0) {
#pragma unroll
        for (int s = 0; s < NTILES; s++)
            mbar_init(mb0 + 8 * s, 1);
    }
    __syncthreads();

    // Producer: issue all tile copies up-front (async engine holds the MLP).
    if (tid == 0) {
#pragma unroll
        for (int s = 0; s < NTILES; s++) {
            int rows = batch - base_row - s * ROWS_PER_TILE;
            rows = rows < 0 ? 0 : (rows > ROWS_PER_TILE ? ROWS_PER_TILE : rows);
            if (rows > 0) {
                const uint32_t bytes = (uint32_t)rows * (N_STATE * 4);
                mbar_expect_tx(mb0 + 8 * s, bytes);
                bulk_copy(smem_u32(&tiles[s][0]),
                          x0 + (size_t)(base_row + s * ROWS_PER_TILE) * 10,
                          bytes, mb0 + 8 * s);
            }
        }
    }

    const int lane = tid & 31;
    if (lane >= 30) return;                 // lanes 30,31 idle (in no shfl mask)

    const int g = (lane >= 20) ? 2 : (lane >= 10 ? 1 : 0);  // row-pair group
    const int t = lane - g * 10;                            // element chunk
    const int warp = tid >> 5;

    const unsigned mask = 0x3FFu << (g * 10);
    const int base = g * 10;
    const int left  = (t == 0) ? base + 9 : lane - 1;
    const int right = (t == 9) ? base     : lane + 1;

    const float dt = __ldg(dt_ptr);
    const ull dt2  = pack2(dt, dt);
    const ull hdt2 = pack2(0.5f * dt, 0.5f * dt);
    const float sdt = dt * (1.0f / 6.0f);
    const ull sdt2 = pack2(sdt, sdt);

    const int vi = (warp * ROWS_PER_WARP + g) * 10 + t;  // smem float4 index

    int row = base_row + warp * ROWS_PER_WARP + g;       // incremental
    float4* __restrict__ pout = out + ((size_t)row * 10 + t);

#pragma unroll
    for (int s = 0; s < NTILES; s++) {
        if (row >= batch) break;            // later tiles are also out of range
        const bool bOK = (row + 3 < batch);

        mbar_wait0(mb0 + 8 * s);

        const float4 va = tiles[s][vi];
        const float4 vb = bOK ? tiles[s][vi + 30] : va;

        ull x[4] = { pack2(va.x, vb.x), pack2(va.y, vb.y),
                     pack2(va.z, vb.z), pack2(va.w, vb.w) };
        ull acc[4], ya[4], yb[4];

        stage<true,  true >(x,  acc, x, ya, ONE_2, hdt2, mask, left, right);
        stage<false, true >(ya, acc, x, yb, TWO_2, hdt2, mask, left, right);
        stage<false, true >(yb, acc, x, ya, TWO_2, dt2,  mask, left, right);
        stage<false, false>(ya, acc, x, yb, ONE_2, dt2,  mask, left, right);

        float4 oa, ob;
        unpack2(fma2(acc[0], sdt2, x[0]), oa.x, ob.x);
        unpack2(fma2(acc[1], sdt2, x[1]), oa.y, ob.y);
        unpack2(fma2(acc[2], sdt2, x[2]), oa.z, ob.z);
        unpack2(fma2(acc[3], sdt2, x[3]), oa.w, ob.w);

        pout[0] = oa;
        if (bOK) pout[30] = ob;

        row += ROWS_PER_TILE;
        pout += VECS_PER_TILE;
    }
}

extern "C" void kernel_launch(void* const* d_in, const int* in_sizes, int n_in,
                              void* d_out, int out_size) {
    const float4* x0 = (const float4*)d_in[0];
    // d_in[1] is t (unused, autonomous system)
    const float* dt = (const float*)d_in[2];
    float4* out = (float4*)d_out;

    const int batch = in_sizes[0] / N_STATE;
    const int blocks = (batch + ROWS_PER_CTA - 1) / ROWS_PER_CTA;
    lorenz96_rk4_kernel<<<blocks, TPB>>>(x0, dt, out, batch);
}